// round 14
// baseline (speedup 1.0000x reference)
#include <cuda_runtime.h>
#include <math_constants.h>
#include <cuda_fp16.h>
#include <cstdint>

#define N_NODES 50000
#define N_EDGES 800000
#define F_IN 165
#define HID 128
#define NH 4

#define BM 64        // GEMM block tile rows
#define APITCH 24    // halfs per A row (16 data + 8 pad) -> conflict-free ldmatrix
#define BPITCH 136   // halfs per B row (128 data + 8 pad) -> conflict-free ldmatrix.trans
#define EDGE_GRID 592

// ---------------- scratch (device globals) ----------------
__device__ __half g_fth[N_NODES * HID];   // fp16 features for edge gather
__device__ __half g_h1h[N_NODES * HID];   // layer1 output (fp16, feeds GEMM2)
__device__ float  g_el[N_NODES * NH];
__device__ float  g_er[N_NODES * NH];
__device__ int    g_cnt[N_NODES];
__device__ int    g_rowptr[N_NODES + 1];
__device__ int    g_rank[N_EDGES];
__device__ int    g_psrc[N_EDGES];

// host-side stream/event resources (created once; no device memory)
static struct SideRes {
    cudaStream_t s2;
    cudaEvent_t evFork, evJoin;
    SideRes() {
        cudaStreamCreateWithFlags(&s2, cudaStreamNonBlocking);
        cudaEventCreateWithFlags(&evFork, cudaEventDisableTiming);
        cudaEventCreateWithFlags(&evJoin, cudaEventDisableTiming);
    }
} g_res;

__device__ __forceinline__ float lrelu(float x) { return x > 0.f ? x : 0.2f * x; }

__device__ __forceinline__ void ldsm_x4(unsigned* r, unsigned addr) {
    asm volatile("ldmatrix.sync.aligned.m8n8.x4.shared.b16 {%0,%1,%2,%3}, [%4];"
                 : "=r"(r[0]), "=r"(r[1]), "=r"(r[2]), "=r"(r[3]) : "r"(addr));
}
__device__ __forceinline__ void ldsm_x4_trans(unsigned* r, unsigned addr) {
    asm volatile("ldmatrix.sync.aligned.m8n8.x4.trans.shared.b16 {%0,%1,%2,%3}, [%4];"
                 : "=r"(r[0]), "=r"(r[1]), "=r"(r[2]), "=r"(r[3]) : "r"(addr));
}
__device__ __forceinline__ void mma_fp16(float* c, const unsigned* a, unsigned b0, unsigned b1) {
    asm volatile(
        "mma.sync.aligned.m16n8k16.row.col.f32.f16.f16.f32 "
        "{%0,%1,%2,%3}, {%4,%5,%6,%7}, {%8,%9}, {%0,%1,%2,%3};\n"
        : "+f"(c[0]), "+f"(c[1]), "+f"(c[2]), "+f"(c[3])
        : "r"(a[0]), "r"(a[1]), "r"(a[2]), "r"(a[3]), "r"(b0), "r"(b1));
}

// ================= CSR build =================
__global__ void hist_kernel(const int* __restrict__ dst, int* cnt, int* rank) {
    int idx = blockIdx.x * blockDim.x + threadIdx.x;
    int stride = gridDim.x * blockDim.x;
#pragma unroll
    for (int k = 0; k < 4; k++) {
        int e = idx + k * stride;
        if (e < N_EDGES) rank[e] = atomicAdd(&cnt[__ldg(&dst[e])], 1);
    }
}

__global__ void scan_kernel(const int* __restrict__ cnt, int* rowptr) {
    __shared__ int partial[1024];
    const int CH = (N_NODES + 1023) / 1024;
    int t = threadIdx.x;
    int base = t * CH;
    int sum = 0;
    for (int i = 0; i < CH; i++) {
        int idx = base + i;
        if (idx < N_NODES) sum += cnt[idx];
    }
    partial[t] = sum;
    __syncthreads();
    for (int off = 1; off < 1024; off <<= 1) {
        int v = (t >= off) ? partial[t - off] : 0;
        __syncthreads();
        partial[t] += v;
        __syncthreads();
    }
    int run = (t > 0) ? partial[t - 1] : 0;
    for (int i = 0; i < CH; i++) {
        int idx = base + i;
        if (idx < N_NODES) {
            rowptr[idx] = run;
            run += cnt[idx];
        }
    }
    if (t == 1023) rowptr[N_NODES] = partial[1023];
}

__global__ void scatter_kernel(const int* __restrict__ src, const int* __restrict__ dst,
                               const int* __restrict__ rowptr, const int* __restrict__ rank,
                               int* psrc) {
    int idx = blockIdx.x * blockDim.x + threadIdx.x;
    int stride = gridDim.x * blockDim.x;
#pragma unroll
    for (int k = 0; k < 4; k++) {
        int e = idx + k * stride;
        if (e < N_EDGES)
            psrc[__ldg(&rowptr[__ldg(&dst[e])]) + __ldg(&rank[e])] = __ldg(&src[e]);
    }
}

// ================= FP16 tensor-core GEMM + fused el/er epilogue =================
// Block tile 64x128, 8 warps (warp tile 16x64), 3 CTAs/SM. (round-11 measured-good config)
template <typename TIn>
__global__ __launch_bounds__(256, 3) void gemm_fp16(const TIn* __restrict__ X,
                                                    const float* __restrict__ W,
                                                    const float* __restrict__ al,
                                                    const float* __restrict__ ar,
                                                    __half* __restrict__ Yh,
                                                    float* __restrict__ el,
                                                    float* __restrict__ er,
                                                    int N, int K) {
    __shared__ __half As[2][BM * APITCH];
    __shared__ __half Bs[2][16 * BPITCH];
    __shared__ float el_s[BM * NH], er_s[BM * NH];
    __shared__ float als[HID], ars[HID];

    int t = threadIdx.x;
    int warp = t >> 5, lane = t & 31;
    int g = lane >> 2, tid = lane & 3;
    int wm = (warp >> 1) * 16;
    int wn = (warp & 1) * 64;
    int bm = blockIdx.x * BM;

    if (t < HID) {
        als[t] = al[t];
        ars[t] = ar[t];
    }
    el_s[t] = 0.f;
    er_s[t] = 0.f;

    float acc[8][4];
#pragma unroll
    for (int j = 0; j < 8; j++)
#pragma unroll
        for (int q = 0; q < 4; q++) acc[j][q] = 0.f;

    const int KT = (K + 15) / 16;

    const int kk = t & 15;
    const int ar4 = t >> 4;
    const int kk2 = (t & 7) * 2;
    const int ar2 = t >> 3;
    const int kb = t >> 4, cb = (t & 15) * 8;

    float aF[4];
    __half2 aH[2];
    float4 bReg0, bReg1;

    auto load_regs = [&](int k0) {
        if constexpr (sizeof(TIn) == 4) {
            int gk = k0 + kk;
            bool kok = gk < K;
#pragma unroll
            for (int p = 0; p < 4; p++) {
                int gr = bm + ar4 + 16 * p;
                bool ok = kok && gr < N;
                aF[p] = ok ? __ldg((const float*)X + (long)gr * K + gk) : 0.f;
            }
        } else {
            int gk = k0 + kk2;
            bool kok = gk < K;
#pragma unroll
            for (int p = 0; p < 2; p++) {
                int gr = bm + ar2 + 32 * p;
                bool ok = kok && gr < N;
                aH[p] = ok ? *(const __half2*)((const __half*)X + (long)gr * K + gk)
                           : __half2half2(__float2half(0.f));
            }
        }
        int gkb = k0 + kb;
        if (gkb < K) {
            bReg0 = *(const float4*)&W[gkb * HID + cb];
            bReg1 = *(const float4*)&W[gkb * HID + cb + 4];
        } else {
            bReg0 = bReg1 = make_float4(0.f, 0.f, 0.f, 0.f);
        }
    };

    auto store_smem = [&](int buf) {
        if constexpr (sizeof(TIn) == 4) {
#pragma unroll
            for (int p = 0; p < 4; p++)
                As[buf][(ar4 + 16 * p) * APITCH + kk] = __float2half_rn(aF[p]);
        } else {
#pragma unroll
            for (int p = 0; p < 2; p++)
                *(__half2*)&As[buf][(ar2 + 32 * p) * APITCH + kk2] = aH[p];
        }
        __half2* bp = (__half2*)&Bs[buf][kb * BPITCH + cb];
        bp[0] = __floats2half2_rn(bReg0.x, bReg0.y);
        bp[1] = __floats2half2_rn(bReg0.z, bReg0.w);
        bp[2] = __floats2half2_rn(bReg1.x, bReg1.y);
        bp[3] = __floats2half2_rn(bReg1.z, bReg1.w);
    };

    unsigned aoff;
    {
        int m = wm + (lane & 7) + ((lane >> 3) & 1) * 8;
        int k = (lane >> 4) * 8;
        aoff = (unsigned)((m * APITCH + k) * 2);
    }
    unsigned boff[4];
#pragma unroll
    for (int p = 0; p < 4; p++) {
        int k = (lane & 7) + ((lane >> 3) & 1) * 8;
        int n = wn + (2 * p + (lane >> 4)) * 8;
        boff[p] = (unsigned)((k * BPITCH + n) * 2);
    }

    load_regs(0);
    store_smem(0);

    for (int kt = 0; kt < KT; kt++) {
        __syncthreads();
        int buf = kt & 1;
        if (kt + 1 < KT) load_regs((kt + 1) * 16);

        unsigned aBase = (unsigned)__cvta_generic_to_shared(&As[buf][0]);
        unsigned bBase = (unsigned)__cvta_generic_to_shared(&Bs[buf][0]);

        unsigned af[4], bf[4][4];
        ldsm_x4(af, aBase + aoff);
#pragma unroll
        for (int p = 0; p < 4; p++) ldsm_x4_trans(bf[p], bBase + boff[p]);

#pragma unroll
        for (int j = 0; j < 8; j++) {
            const unsigned* bj = bf[j >> 1];
            int o = (j & 1) * 2;
            mma_fp16(acc[j], af, bj[o], bj[o + 1]);
        }

        if (kt + 1 < KT) store_smem((kt + 1) & 1);
    }

    // ---- epilogue: fp16 ft store + fused el/er partials ----
    {
        int lr0 = wm + g;
        int lr1 = lr0 + 8;
        int r0 = bm + lr0, r1 = bm + lr1;
#pragma unroll
        for (int j = 0; j < 8; j++) {
            int c = wn + j * 8 + tid * 2;
            if (r0 < N) *(__half2*)&Yh[r0 * HID + c] = __floats2half2_rn(acc[j][0], acc[j][1]);
            if (r1 < N) *(__half2*)&Yh[r1 * HID + c] = __floats2half2_rn(acc[j][2], acc[j][3]);
        }
#pragma unroll
        for (int half = 0; half < 2; half++) {
            float pl0 = 0.f, pr0 = 0.f, pl1 = 0.f, pr1 = 0.f;
#pragma unroll
            for (int jj = 0; jj < 4; jj++) {
                int j = half * 4 + jj;
                int c = wn + j * 8 + tid * 2;
                float a0 = als[c], a1 = als[c + 1];
                float b0 = ars[c], b1 = ars[c + 1];
                pl0 += acc[j][0] * a0 + acc[j][1] * a1;
                pr0 += acc[j][0] * b0 + acc[j][1] * b1;
                pl1 += acc[j][2] * a0 + acc[j][3] * a1;
                pr1 += acc[j][2] * b0 + acc[j][3] * b1;
            }
            int h = (wn >> 5) + half;
            atomicAdd(&el_s[lr0 * NH + h], pl0);
            atomicAdd(&er_s[lr0 * NH + h], pr0);
            atomicAdd(&el_s[lr1 * NH + h], pl1);
            atomicAdd(&er_s[lr1 * NH + h], pr1);
        }
    }
    __syncthreads();
    if (t < BM) {
        int n = bm + t;
        if (n < N) {
            *(float4*)&el[n * NH] = *(float4*)&el_s[t * NH];
            *(float4*)&er[n * NH] = *(float4*)&er_s[t * NH];
        }
    }
}

// ================= single-pass fused edge softmax + aggregation =================
// grid-stride: each warp handles ~10 nodes -> load imbalance averages out.
template <bool FINAL>
__global__ __launch_bounds__(256, 4) void gat_edge_kernel(
    const int* __restrict__ rowptr, const int* __restrict__ psrc,
    const float* __restrict__ el, const float* __restrict__ er,
    const __half* __restrict__ fth, const float* __restrict__ bias,
    void* __restrict__ out) {
    int lane = threadIdx.x;
    int h = lane >> 3;
    float4 b4 = *(const float4*)&bias[lane * 4];
    const int step = gridDim.x * 8;

    for (int n = blockIdx.x * 8 + threadIdx.y; n < N_NODES; n += step) {
        int beg = rowptr[n], deg = rowptr[n + 1] - beg;
        float ern = __ldg(&er[n * NH + h]);

        float sum = 0.f;
        float4 acc0 = make_float4(0.f, 0.f, 0.f, 0.f);
        float4 acc1 = make_float4(0.f, 0.f, 0.f, 0.f);

        int i = 0;
        for (; i + 4 <= deg; i += 4) {
            int s0 = __ldg(&psrc[beg + i]);
            int s1 = __ldg(&psrc[beg + i + 1]);
            int s2 = __ldg(&psrc[beg + i + 2]);
            int s3 = __ldg(&psrc[beg + i + 3]);
            float e0 = __ldg(&el[s0 * NH + h]);
            float e1 = __ldg(&el[s1 * NH + h]);
            float e2 = __ldg(&el[s2 * NH + h]);
            float e3 = __ldg(&el[s3 * NH + h]);
            uint2 u0 = *(const uint2*)&fth[s0 * HID + lane * 4];
            uint2 u1 = *(const uint2*)&fth[s1 * HID + lane * 4];
            uint2 u2 = *(const uint2*)&fth[s2 * HID + lane * 4];
            uint2 u3 = *(const uint2*)&fth[s3 * HID + lane * 4];
            float v0 = __expf(lrelu(e0 + ern));
            float v1 = __expf(lrelu(e1 + ern));
            float v2 = __expf(lrelu(e2 + ern));
            float v3 = __expf(lrelu(e3 + ern));
            sum += (v0 + v1) + (v2 + v3);
            float2 f0a = __half22float2(*(__half2*)&u0.x), f0b = __half22float2(*(__half2*)&u0.y);
            float2 f1a = __half22float2(*(__half2*)&u1.x), f1b = __half22float2(*(__half2*)&u1.y);
            float2 f2a = __half22float2(*(__half2*)&u2.x), f2b = __half22float2(*(__half2*)&u2.y);
            float2 f3a = __half22float2(*(__half2*)&u3.x), f3b = __half22float2(*(__half2*)&u3.y);
            acc0.x += v0 * f0a.x + v2 * f2a.x;
            acc0.y += v0 * f0a.y + v2 * f2a.y;
            acc0.z += v0 * f0b.x + v2 * f2b.x;
            acc0.w += v0 * f0b.y + v2 * f2b.y;
            acc1.x += v1 * f1a.x + v3 * f3a.x;
            acc1.y += v1 * f1a.y + v3 * f3a.y;
            acc1.z += v1 * f1b.x + v3 * f3b.x;
            acc1.w += v1 * f1b.y + v3 * f3b.y;
        }
        for (; i < deg; i++) {
            int s = __ldg(&psrc[beg + i]);
            float v = __expf(lrelu(__ldg(&el[s * NH + h]) + ern));
            uint2 u = *(const uint2*)&fth[s * HID + lane * 4];
            float2 fa = __half22float2(*(__half2*)&u.x), fb = __half22float2(*(__half2*)&u.y);
            sum += v;
            acc0.x += v * fa.x; acc0.y += v * fa.y; acc0.z += v * fb.x; acc0.w += v * fb.y;
        }

        float inv = 1.f / sum;
        float4 r;
        r.x = (acc0.x + acc1.x) * inv + b4.x;
        r.y = (acc0.y + acc1.y) * inv + b4.y;
        r.z = (acc0.z + acc1.z) * inv + b4.z;
        r.w = (acc0.w + acc1.w) * inv + b4.w;

        if (FINAL) {
            float v = r.x + r.y + r.z + r.w;
#pragma unroll
            for (int off = 16; off >= 1; off >>= 1)
                v += __shfl_xor_sync(0xffffffffu, v, off);
            if (lane == 0) ((float*)out)[n] = v * (1.0f / HID);
        } else {
            __half2 p0 = __floats2half2_rn(r.x, r.y);
            __half2 p1 = __floats2half2_rn(r.z, r.w);
            uint2 w;
            w.x = *(unsigned*)&p0;
            w.y = *(unsigned*)&p1;
            *(uint2*)&((__half*)out)[n * HID + lane * 4] = w;
        }
    }
}

// ================= launch =================
extern "C" void kernel_launch(void* const* d_in, const int* in_sizes, int n_in,
                              void* d_out, int out_size) {
    const float* features = (const float*)d_in[0];
    const float* W1  = (const float*)d_in[1];
    const float* al1 = (const float*)d_in[2];
    const float* ar1 = (const float*)d_in[3];
    const float* b1  = (const float*)d_in[4];
    const float* W2  = (const float*)d_in[5];
    const float* al2 = (const float*)d_in[6];
    const float* ar2 = (const float*)d_in[7];
    const float* b2  = (const float*)d_in[8];
    const int*   src = (const int*)d_in[9];
    const int*   dst = (const int*)d_in[10];
    float* out = (float*)d_out;

    __half *fth, *h1h;
    float *el, *er;
    int *cnt, *rowptr, *rank, *psrc;
    cudaGetSymbolAddress((void**)&fth, g_fth);
    cudaGetSymbolAddress((void**)&h1h, g_h1h);
    cudaGetSymbolAddress((void**)&el, g_el);
    cudaGetSymbolAddress((void**)&er, g_er);
    cudaGetSymbolAddress((void**)&cnt, g_cnt);
    cudaGetSymbolAddress((void**)&rowptr, g_rowptr);
    cudaGetSymbolAddress((void**)&rank, g_rank);
    cudaGetSymbolAddress((void**)&psrc, g_psrc);

    const int edgeBlocks4 = (N_EDGES + 4 * 256 - 1) / (4 * 256);
    const int gemmBlocks = (N_NODES + BM - 1) / BM;
    dim3 warpBlk(32, 8);

    // ---- fork: CSR build on side stream, GEMM1 on main stream ----
    cudaEventRecord(g_res.evFork, 0);
    cudaStreamWaitEvent(g_res.s2, g_res.evFork, 0);

    cudaMemsetAsync(cnt, 0, N_NODES * sizeof(int), g_res.s2);
    hist_kernel<<<edgeBlocks4, 256, 0, g_res.s2>>>(dst, cnt, rank);
    scan_kernel<<<1, 1024, 0, g_res.s2>>>(cnt, rowptr);
    scatter_kernel<<<edgeBlocks4, 256, 0, g_res.s2>>>(src, dst, rowptr, rank, psrc);
    cudaEventRecord(g_res.evJoin, g_res.s2);

    gemm_fp16<float><<<gemmBlocks, 256>>>(features, W1, al1, ar1, fth, el, er, N_NODES, F_IN);

    // ---- join ----
    cudaStreamWaitEvent(0, g_res.evJoin, 0);

    // ---- layer 1 edge (writes fp16 h1) ----
    gat_edge_kernel<false><<<EDGE_GRID, warpBlk>>>(rowptr, psrc, el, er, fth, b1, h1h);

    // ---- layer 2 ----
    gemm_fp16<__half><<<gemmBlocks, 256>>>(h1h, W2, al2, ar2, fth, el, er, N_NODES, HID);
    gat_edge_kernel<true><<<EDGE_GRID, warpBlk>>>(rowptr, psrc, el, er, fth, b2, out);
}

// round 15
// speedup vs baseline: 1.1576x; 1.1576x over previous
#include <cuda_runtime.h>
#include <math_constants.h>
#include <cuda_fp16.h>
#include <cstdint>

#define N_NODES 50000
#define N_EDGES 800000
#define F_IN 165
#define HID 128
#define NH 4

#define BM 64        // GEMM row-tile
#define APITCH 24    // halfs per A row -> conflict-free ldmatrix
#define BPITCH 136   // halfs per B row -> conflict-free ldmatrix.trans
#define KT_MAX 11    // ceil(165/16)
#define BS_HALFS (KT_MAX * 16 * BPITCH)
#define AS_HALFS (2 * BM * APITCH)
#define WRES_SMEM_BYTES ((BS_HALFS + AS_HALFS) * 2 + (2 * BM * NH + 2 * HID) * 4)
#define WRES_GRID 444
#define EDGE_GRID 592

// ---------------- scratch (device globals) ----------------
__device__ __half g_fth[N_NODES * HID];
__device__ __half g_h1h[N_NODES * HID];
__device__ float  g_el[N_NODES * NH];
__device__ float  g_er[N_NODES * NH];
__device__ int    g_cnt[N_NODES];
__device__ int    g_rowptr[N_NODES + 1];
__device__ int    g_rank[N_EDGES];
__device__ int    g_psrc[N_EDGES];

static struct SideRes {
    cudaStream_t s2;
    cudaEvent_t evFork, evJoin;
    SideRes() {
        cudaStreamCreateWithFlags(&s2, cudaStreamNonBlocking);
        cudaEventCreateWithFlags(&evFork, cudaEventDisableTiming);
        cudaEventCreateWithFlags(&evJoin, cudaEventDisableTiming);
    }
} g_res;

__device__ __forceinline__ float lrelu(float x) { return x > 0.f ? x : 0.2f * x; }

__device__ __forceinline__ void ldsm_x4(unsigned* r, unsigned addr) {
    asm volatile("ldmatrix.sync.aligned.m8n8.x4.shared.b16 {%0,%1,%2,%3}, [%4];"
                 : "=r"(r[0]), "=r"(r[1]), "=r"(r[2]), "=r"(r[3]) : "r"(addr));
}
__device__ __forceinline__ void ldsm_x4_trans(unsigned* r, unsigned addr) {
    asm volatile("ldmatrix.sync.aligned.m8n8.x4.trans.shared.b16 {%0,%1,%2,%3}, [%4];"
                 : "=r"(r[0]), "=r"(r[1]), "=r"(r[2]), "=r"(r[3]) : "r"(addr));
}
__device__ __forceinline__ void mma_fp16(float* c, const unsigned* a, unsigned b0, unsigned b1) {
    asm volatile(
        "mma.sync.aligned.m16n8k16.row.col.f32.f16.f16.f32 "
        "{%0,%1,%2,%3}, {%4,%5,%6,%7}, {%8,%9}, {%0,%1,%2,%3};\n"
        : "+f"(c[0]), "+f"(c[1]), "+f"(c[2]), "+f"(c[3])
        : "r"(a[0]), "r"(a[1]), "r"(a[2]), "r"(a[3]), "r"(b0), "r"(b1));
}

// ================= CSR build =================
__global__ void hist_kernel(const int* __restrict__ dst, int* cnt, int* rank) {
    int idx = blockIdx.x * blockDim.x + threadIdx.x;
    int stride = gridDim.x * blockDim.x;
#pragma unroll
    for (int k = 0; k < 4; k++) {
        int e = idx + k * stride;
        if (e < N_EDGES) rank[e] = atomicAdd(&cnt[__ldg(&dst[e])], 1);
    }
}

__global__ void scan_kernel(const int* __restrict__ cnt, int* rowptr) {
    __shared__ int partial[1024];
    const int CH = (N_NODES + 1023) / 1024;
    int t = threadIdx.x;
    int base = t * CH;
    int sum = 0;
    for (int i = 0; i < CH; i++) {
        int idx = base + i;
        if (idx < N_NODES) sum += cnt[idx];
    }
    partial[t] = sum;
    __syncthreads();
    for (int off = 1; off < 1024; off <<= 1) {
        int v = (t >= off) ? partial[t - off] : 0;
        __syncthreads();
        partial[t] += v;
        __syncthreads();
    }
    int run = (t > 0) ? partial[t - 1] : 0;
    for (int i = 0; i < CH; i++) {
        int idx = base + i;
        if (idx < N_NODES) {
            rowptr[idx] = run;
            run += cnt[idx];
        }
    }
    if (t == 1023) rowptr[N_NODES] = partial[1023];
}

__global__ void scatter_kernel(const int* __restrict__ src, const int* __restrict__ dst,
                               const int* __restrict__ rowptr, const int* __restrict__ rank,
                               int* psrc) {
    int idx = blockIdx.x * blockDim.x + threadIdx.x;
    int stride = gridDim.x * blockDim.x;
#pragma unroll
    for (int k = 0; k < 4; k++) {
        int e = idx + k * stride;
        if (e < N_EDGES)
            psrc[__ldg(&rowptr[__ldg(&dst[e])]) + __ldg(&rank[e])] = __ldg(&src[e]);
    }
}

// ================= GEMM1: W-resident persistent (64 regs -> CSR co-resides) =================
__global__ __launch_bounds__(256) void gemm_wres(const float* __restrict__ X,
                                                 const float* __restrict__ W,
                                                 const float* __restrict__ al,
                                                 const float* __restrict__ ar,
                                                 __half* __restrict__ Yh,
                                                 float* __restrict__ el,
                                                 float* __restrict__ er,
                                                 int N, int K) {
    extern __shared__ char smraw[];
    __half* Bs = (__half*)smraw;
    __half* As = (__half*)smraw + BS_HALFS;
    float* el_s = (float*)(smraw + (BS_HALFS + AS_HALFS) * 2);
    float* er_s = el_s + BM * NH;
    float* als = er_s + BM * NH;
    float* ars = als + HID;

    int t = threadIdx.x;
    int warp = t >> 5, lane = t & 31;
    int g = lane >> 2, tid = lane & 3;
    int wm = (warp >> 1) * 16;
    int wn = (warp & 1) * 64;

    const int KT = (K + 15) / 16;

    if (t < HID) {
        als[t] = al[t];
        ars[t] = ar[t];
    }

    // ---- W -> Bs, once per CTA ----
    const int kb = t >> 4, cb = (t & 15) * 8;
    for (int kc = 0; kc < KT; kc++) {
        int gk = kc * 16 + kb;
        float4 v0, v1;
        if (gk < K) {
            v0 = *(const float4*)&W[gk * HID + cb];
            v1 = *(const float4*)&W[gk * HID + cb + 4];
        } else {
            v0 = v1 = make_float4(0.f, 0.f, 0.f, 0.f);
        }
        __half2* bp = (__half2*)&Bs[(kc * 16 + kb) * BPITCH + cb];
        bp[0] = __floats2half2_rn(v0.x, v0.y);
        bp[1] = __floats2half2_rn(v0.z, v0.w);
        bp[2] = __floats2half2_rn(v1.x, v1.y);
        bp[3] = __floats2half2_rn(v1.z, v1.w);
    }

    const int kkA = t & 15;
    const int ar4 = t >> 4;

    unsigned aoff;
    {
        int m = wm + (lane & 7) + ((lane >> 3) & 1) * 8;
        int k = (lane >> 4) * 8;
        aoff = (unsigned)((m * APITCH + k) * 2);
    }
    unsigned boff[4];
#pragma unroll
    for (int p = 0; p < 4; p++) {
        int k = (lane & 7) + ((lane >> 3) & 1) * 8;
        int n = wn + (2 * p + (lane >> 4)) * 8;
        boff[p] = (unsigned)((k * BPITCH + n) * 2);
    }
    const unsigned aBase0 = (unsigned)__cvta_generic_to_shared(As);
    const unsigned bBase0 = (unsigned)__cvta_generic_to_shared(Bs);

    int bm = 0;
    float aF[4];

    auto load_regs = [&](int k0) {
        int gk = k0 + kkA;
        bool kok = gk < K;
#pragma unroll
        for (int p = 0; p < 4; p++) {
            int gr = bm + ar4 + 16 * p;
            bool ok = kok && gr < N;
            aF[p] = ok ? __ldg(&X[(long)gr * K + gk]) : 0.f;
        }
    };
    auto store_smem = [&](int buf) {
        __half* Ab = As + buf * BM * APITCH;
#pragma unroll
        for (int p = 0; p < 4; p++)
            Ab[(ar4 + 16 * p) * APITCH + kkA] = __float2half_rn(aF[p]);
    };

    for (int tile = blockIdx.x; tile * BM < N; tile += gridDim.x) {
        bm = tile * BM;
        el_s[t] = 0.f;
        er_s[t] = 0.f;

        float acc[8][4];
#pragma unroll
        for (int j = 0; j < 8; j++)
#pragma unroll
            for (int q = 0; q < 4; q++) acc[j][q] = 0.f;

        load_regs(0);
        store_smem(0);

        for (int kt = 0; kt < KT; kt++) {
            __syncthreads();
            int buf = kt & 1;
            if (kt + 1 < KT) load_regs((kt + 1) * 16);

            unsigned aBase = aBase0 + buf * BM * APITCH * 2;
            unsigned bChunk = bBase0 + kt * 16 * BPITCH * 2;

            unsigned af[4], bfr[4][4];
            ldsm_x4(af, aBase + aoff);
#pragma unroll
            for (int p = 0; p < 4; p++) ldsm_x4_trans(bfr[p], bChunk + boff[p]);

#pragma unroll
            for (int j = 0; j < 8; j++) {
                const unsigned* bj = bfr[j >> 1];
                int o = (j & 1) * 2;
                mma_fp16(acc[j], af, bj[o], bj[o + 1]);
            }

            if (kt + 1 < KT) store_smem((kt + 1) & 1);
        }

        {
            int lr0 = wm + g;
            int lr1 = lr0 + 8;
            int r0 = bm + lr0, r1 = bm + lr1;
#pragma unroll
            for (int j = 0; j < 8; j++) {
                int c = wn + j * 8 + tid * 2;
                if (r0 < N) *(__half2*)&Yh[r0 * HID + c] = __floats2half2_rn(acc[j][0], acc[j][1]);
                if (r1 < N) *(__half2*)&Yh[r1 * HID + c] = __floats2half2_rn(acc[j][2], acc[j][3]);
            }
#pragma unroll
            for (int half = 0; half < 2; half++) {
                float pl0 = 0.f, pr0 = 0.f, pl1 = 0.f, pr1 = 0.f;
#pragma unroll
                for (int jj = 0; jj < 4; jj++) {
                    int j = half * 4 + jj;
                    int c = wn + j * 8 + tid * 2;
                    float a0 = als[c], a1 = als[c + 1];
                    float b0 = ars[c], b1 = ars[c + 1];
                    pl0 += acc[j][0] * a0 + acc[j][1] * a1;
                    pr0 += acc[j][0] * b0 + acc[j][1] * b1;
                    pl1 += acc[j][2] * a0 + acc[j][3] * a1;
                    pr1 += acc[j][2] * b0 + acc[j][3] * b1;
                }
                int h = (wn >> 5) + half;
                atomicAdd(&el_s[lr0 * NH + h], pl0);
                atomicAdd(&er_s[lr0 * NH + h], pr0);
                atomicAdd(&el_s[lr1 * NH + h], pl1);
                atomicAdd(&er_s[lr1 * NH + h], pr1);
            }
        }
        __syncthreads();
        if (t < BM) {
            int n = bm + t;
            if (n < N) {
                *(float4*)&el[n * NH] = *(float4*)&el_s[t * NH];
                *(float4*)&er[n * NH] = *(float4*)&er_s[t * NH];
            }
        }
        __syncthreads();
    }
}

// ================= GEMM2: static double-buffered (measured 32.8us) =================
__global__ __launch_bounds__(256, 3) void gemm_static(const __half* __restrict__ X,
                                                      const float* __restrict__ W,
                                                      const float* __restrict__ al,
                                                      const float* __restrict__ ar,
                                                      __half* __restrict__ Yh,
                                                      float* __restrict__ el,
                                                      float* __restrict__ er,
                                                      int N, int K) {
    __shared__ __half As[2][BM * APITCH];
    __shared__ __half Bs[2][16 * BPITCH];
    __shared__ float el_s[BM * NH], er_s[BM * NH];
    __shared__ float als[HID], ars[HID];

    int t = threadIdx.x;
    int warp = t >> 5, lane = t & 31;
    int g = lane >> 2, tid = lane & 3;
    int wm = (warp >> 1) * 16;
    int wn = (warp & 1) * 64;
    int bm = blockIdx.x * BM;

    if (t < HID) {
        als[t] = al[t];
        ars[t] = ar[t];
    }
    el_s[t] = 0.f;
    er_s[t] = 0.f;

    float acc[8][4];
#pragma unroll
    for (int j = 0; j < 8; j++)
#pragma unroll
        for (int q = 0; q < 4; q++) acc[j][q] = 0.f;

    const int KT = (K + 15) / 16;

    const int kk2 = (t & 7) * 2;
    const int ar2 = t >> 3;
    const int kb = t >> 4, cb = (t & 15) * 8;

    __half2 aH[2];
    float4 bReg0, bReg1;

    auto load_regs = [&](int k0) {
        int gk = k0 + kk2;
        bool kok = gk < K;
#pragma unroll
        for (int p = 0; p < 2; p++) {
            int gr = bm + ar2 + 32 * p;
            bool ok = kok && gr < N;
            aH[p] = ok ? *(const __half2*)(X + (long)gr * K + gk)
                       : __half2half2(__float2half(0.f));
        }
        int gkb = k0 + kb;
        if (gkb < K) {
            bReg0 = *(const float4*)&W[gkb * HID + cb];
            bReg1 = *(const float4*)&W[gkb * HID + cb + 4];
        } else {
            bReg0 = bReg1 = make_float4(0.f, 0.f, 0.f, 0.f);
        }
    };

    auto store_smem = [&](int buf) {
#pragma unroll
        for (int p = 0; p < 2; p++)
            *(__half2*)&As[buf][(ar2 + 32 * p) * APITCH + kk2] = aH[p];
        __half2* bp = (__half2*)&Bs[buf][kb * BPITCH + cb];
        bp[0] = __floats2half2_rn(bReg0.x, bReg0.y);
        bp[1] = __floats2half2_rn(bReg0.z, bReg0.w);
        bp[2] = __floats2half2_rn(bReg1.x, bReg1.y);
        bp[3] = __floats2half2_rn(bReg1.z, bReg1.w);
    };

    unsigned aoff;
    {
        int m = wm + (lane & 7) + ((lane >> 3) & 1) * 8;
        int k = (lane >> 4) * 8;
        aoff = (unsigned)((m * APITCH + k) * 2);
    }
    unsigned boff[4];
#pragma unroll
    for (int p = 0; p < 4; p++) {
        int k = (lane & 7) + ((lane >> 3) & 1) * 8;
        int n = wn + (2 * p + (lane >> 4)) * 8;
        boff[p] = (unsigned)((k * BPITCH + n) * 2);
    }

    load_regs(0);
    store_smem(0);

    for (int kt = 0; kt < KT; kt++) {
        __syncthreads();
        int buf = kt & 1;
        if (kt + 1 < KT) load_regs((kt + 1) * 16);

        unsigned aBase = (unsigned)__cvta_generic_to_shared(&As[buf][0]);
        unsigned bBase = (unsigned)__cvta_generic_to_shared(&Bs[buf][0]);

        unsigned af[4], bf[4][4];
        ldsm_x4(af, aBase + aoff);
#pragma unroll
        for (int p = 0; p < 4; p++) ldsm_x4_trans(bf[p], bBase + boff[p]);

#pragma unroll
        for (int j = 0; j < 8; j++) {
            const unsigned* bj = bf[j >> 1];
            int o = (j & 1) * 2;
            mma_fp16(acc[j], af, bj[o], bj[o + 1]);
        }

        if (kt + 1 < KT) store_smem((kt + 1) & 1);
    }

    {
        int lr0 = wm + g;
        int lr1 = lr0 + 8;
        int r0 = bm + lr0, r1 = bm + lr1;
#pragma unroll
        for (int j = 0; j < 8; j++) {
            int c = wn + j * 8 + tid * 2;
            if (r0 < N) *(__half2*)&Yh[r0 * HID + c] = __floats2half2_rn(acc[j][0], acc[j][1]);
            if (r1 < N) *(__half2*)&Yh[r1 * HID + c] = __floats2half2_rn(acc[j][2], acc[j][3]);
        }
#pragma unroll
        for (int half = 0; half < 2; half++) {
            float pl0 = 0.f, pr0 = 0.f, pl1 = 0.f, pr1 = 0.f;
#pragma unroll
            for (int jj = 0; jj < 4; jj++) {
                int j = half * 4 + jj;
                int c = wn + j * 8 + tid * 2;
                float a0 = als[c], a1 = als[c + 1];
                float b0 = ars[c], b1 = ars[c + 1];
                pl0 += acc[j][0] * a0 + acc[j][1] * a1;
                pr0 += acc[j][0] * b0 + acc[j][1] * b1;
                pl1 += acc[j][2] * a0 + acc[j][3] * a1;
                pr1 += acc[j][2] * b0 + acc[j][3] * b1;
            }
            int h = (wn >> 5) + half;
            atomicAdd(&el_s[lr0 * NH + h], pl0);
            atomicAdd(&er_s[lr0 * NH + h], pr0);
            atomicAdd(&el_s[lr1 * NH + h], pl1);
            atomicAdd(&er_s[lr1 * NH + h], pr1);
        }
    }
    __syncthreads();
    if (t < BM) {
        int n = bm + t;
        if (n < N) {
            *(float4*)&el[n * NH] = *(float4*)&el_s[t * NH];
            *(float4*)&er[n * NH] = *(float4*)&er_s[t * NH];
        }
    }
}

// ================= single-pass fused edge softmax + aggregation =================
template <bool FINAL>
__global__ __launch_bounds__(256, 4) void gat_edge_kernel(
    const int* __restrict__ rowptr, const int* __restrict__ psrc,
    const float* __restrict__ el, const float* __restrict__ er,
    const __half* __restrict__ fth, const float* __restrict__ bias,
    void* __restrict__ out) {
    int lane = threadIdx.x;
    int h = lane >> 3;
    float4 b4 = *(const float4*)&bias[lane * 4];
    const int step = gridDim.x * 8;

    for (int n = blockIdx.x * 8 + threadIdx.y; n < N_NODES; n += step) {
        int beg = rowptr[n], deg = rowptr[n + 1] - beg;
        float ern = __ldg(&er[n * NH + h]);

        float sum = 0.f;
        float4 acc0 = make_float4(0.f, 0.f, 0.f, 0.f);
        float4 acc1 = make_float4(0.f, 0.f, 0.f, 0.f);

        int i = 0;
        for (; i + 4 <= deg; i += 4) {
            int s0 = __ldg(&psrc[beg + i]);
            int s1 = __ldg(&psrc[beg + i + 1]);
            int s2 = __ldg(&psrc[beg + i + 2]);
            int s3 = __ldg(&psrc[beg + i + 3]);
            float e0 = __ldg(&el[s0 * NH + h]);
            float e1 = __ldg(&el[s1 * NH + h]);
            float e2 = __ldg(&el[s2 * NH + h]);
            float e3 = __ldg(&el[s3 * NH + h]);
            uint2 u0 = *(const uint2*)&fth[s0 * HID + lane * 4];
            uint2 u1 = *(const uint2*)&fth[s1 * HID + lane * 4];
            uint2 u2 = *(const uint2*)&fth[s2 * HID + lane * 4];
            uint2 u3 = *(const uint2*)&fth[s3 * HID + lane * 4];
            float v0 = __expf(lrelu(e0 + ern));
            float v1 = __expf(lrelu(e1 + ern));
            float v2 = __expf(lrelu(e2 + ern));
            float v3 = __expf(lrelu(e3 + ern));
            sum += (v0 + v1) + (v2 + v3);
            float2 f0a = __half22float2(*(__half2*)&u0.x), f0b = __half22float2(*(__half2*)&u0.y);
            float2 f1a = __half22float2(*(__half2*)&u1.x), f1b = __half22float2(*(__half2*)&u1.y);
            float2 f2a = __half22float2(*(__half2*)&u2.x), f2b = __half22float2(*(__half2*)&u2.y);
            float2 f3a = __half22float2(*(__half2*)&u3.x), f3b = __half22float2(*(__half2*)&u3.y);
            acc0.x += v0 * f0a.x + v2 * f2a.x;
            acc0.y += v0 * f0a.y + v2 * f2a.y;
            acc0.z += v0 * f0b.x + v2 * f2b.x;
            acc0.w += v0 * f0b.y + v2 * f2b.y;
            acc1.x += v1 * f1a.x + v3 * f3a.x;
            acc1.y += v1 * f1a.y + v3 * f3a.y;
            acc1.z += v1 * f1b.x + v3 * f3b.x;
            acc1.w += v1 * f1b.y + v3 * f3b.y;
        }
        for (; i < deg; i++) {
            int s = __ldg(&psrc[beg + i]);
            float v = __expf(lrelu(__ldg(&el[s * NH + h]) + ern));
            uint2 u = *(const uint2*)&fth[s * HID + lane * 4];
            float2 fa = __half22float2(*(__half2*)&u.x), fb = __half22float2(*(__half2*)&u.y);
            sum += v;
            acc0.x += v * fa.x; acc0.y += v * fa.y; acc0.z += v * fb.x; acc0.w += v * fb.y;
        }

        float inv = 1.f / sum;
        float4 r;
        r.x = (acc0.x + acc1.x) * inv + b4.x;
        r.y = (acc0.y + acc1.y) * inv + b4.y;
        r.z = (acc0.z + acc1.z) * inv + b4.z;
        r.w = (acc0.w + acc1.w) * inv + b4.w;

        if (FINAL) {
            float v = r.x + r.y + r.z + r.w;
#pragma unroll
            for (int off = 16; off >= 1; off >>= 1)
                v += __shfl_xor_sync(0xffffffffu, v, off);
            if (lane == 0) ((float*)out)[n] = v * (1.0f / HID);
        } else {
            __half2 p0 = __floats2half2_rn(r.x, r.y);
            __half2 p1 = __floats2half2_rn(r.z, r.w);
            uint2 w;
            w.x = *(unsigned*)&p0;
            w.y = *(unsigned*)&p1;
            *(uint2*)&((__half*)out)[n * HID + lane * 4] = w;
        }
    }
}

// ================= launch =================
extern "C" void kernel_launch(void* const* d_in, const int* in_sizes, int n_in,
                              void* d_out, int out_size) {
    const float* features = (const float*)d_in[0];
    const float* W1  = (const float*)d_in[1];
    const float* al1 = (const float*)d_in[2];
    const float* ar1 = (const float*)d_in[3];
    const float* b1  = (const float*)d_in[4];
    const float* W2  = (const float*)d_in[5];
    const float* al2 = (const float*)d_in[6];
    const float* ar2 = (const float*)d_in[7];
    const float* b2  = (const float*)d_in[8];
    const int*   src = (const int*)d_in[9];
    const int*   dst = (const int*)d_in[10];
    float* out = (float*)d_out;

    __half *fth, *h1h;
    float *el, *er;
    int *cnt, *rowptr, *rank, *psrc;
    cudaGetSymbolAddress((void**)&fth, g_fth);
    cudaGetSymbolAddress((void**)&h1h, g_h1h);
    cudaGetSymbolAddress((void**)&el, g_el);
    cudaGetSymbolAddress((void**)&er, g_er);
    cudaGetSymbolAddress((void**)&cnt, g_cnt);
    cudaGetSymbolAddress((void**)&rowptr, g_rowptr);
    cudaGetSymbolAddress((void**)&rank, g_rank);
    cudaGetSymbolAddress((void**)&psrc, g_psrc);

    static bool attrDone = false;
    if (!attrDone) {
        cudaFuncSetAttribute(gemm_wres, cudaFuncAttributeMaxDynamicSharedMemorySize, WRES_SMEM_BYTES);
        attrDone = true;
    }

    const int edgeBlocks4 = (N_EDGES + 4 * 256 - 1) / (4 * 256);
    const int gemm2Blocks = (N_NODES + BM - 1) / BM;
    dim3 warpBlk(32, 8);

    // ---- fork: CSR build on side stream, W-resident GEMM1 on main (64 regs -> co-residency) ----
    cudaEventRecord(g_res.evFork, 0);
    cudaStreamWaitEvent(g_res.s2, g_res.evFork, 0);

    cudaMemsetAsync(cnt, 0, N_NODES * sizeof(int), g_res.s2);
    hist_kernel<<<edgeBlocks4, 256, 0, g_res.s2>>>(dst, cnt, rank);
    scan_kernel<<<1, 1024, 0, g_res.s2>>>(cnt, rowptr);
    scatter_kernel<<<edgeBlocks4, 256, 0, g_res.s2>>>(src, dst, rowptr, rank, psrc);
    cudaEventRecord(g_res.evJoin, g_res.s2);

    gemm_wres<<<WRES_GRID, 256, WRES_SMEM_BYTES>>>(features, W1, al1, ar1, fth, el, er, N_NODES, F_IN);

    // ---- join ----
    cudaStreamWaitEvent(0, g_res.evJoin, 0);

    // ---- layer 1 edge (writes fp16 h1) ----
    gat_edge_kernel<false><<<EDGE_GRID, warpBlk>>>(rowptr, psrc, el, er, fth, b1, h1h);

    // ---- layer 2: fast static GEMM (nothing to overlap) ----
    gemm_static<<<gemm2Blocks, 256>>>(h1h, W2, al2, ar2, fth, el, er, N_NODES, HID);
    gat_edge_kernel<true><<<EDGE_GRID, warpBlk>>>(rowptr, psrc, el, er, fth, b2, out);
}